// round 13
// baseline (speedup 1.0000x reference)
#include <cuda_runtime.h>
#include <cuda_fp16.h>
#include <math.h>
#include <stdint.h>

// Problem constants
#define B    16
#define CIN  256
#define HH   56
#define WW   56
#define E    8
#define COUT 256
#define TAPS 9
#define HW   (HH*WW)                 // 3136
#define BN_EPS 1e-5f

// Conv tiling (fp16, K=16 per mma)
#define CO_T 64        // co per CTA
#define RP   4         // output rows per CTA
#define CI_C 16        // ci chunk (== mma K)
#define NCHUNK 16      // CIN / CI_C
#define NRQ    14      // HH / RP
#define ROWU 480       // uint32 per patch row (60 cols * 8 slots)
#define CHUNK_IN 2880  // 6*480 uint32 per input chunk  (11520 B)
#define CHUNK_W  4608  // 9*4*32*4 uint32 per weight chunk (18432 B)

// Device scratch (allocation-free rule)
__device__ float g_pooled[B*CIN];
__device__ float g_route[B*E];
// frag-order fp16 weights: [b][cot(4)][cic(16)][4608 u32]
__device__ unsigned g_cwf[(size_t)B*4*NCHUNK*CHUNK_W];
// interleaved fp16 input patches: [b][rq(14)][cic(16)][2880 u32]
__device__ unsigned g_xin[(size_t)B*NRQ*NCHUNK*CHUNK_IN];

// ---------------------------------------------------------------------------
__device__ __forceinline__ void mma16(float* c, uint4 a, uint2 b) {
    asm volatile("mma.sync.aligned.m16n8k16.row.col.f32.f16.f16.f32 "
                 "{%0,%1,%2,%3}, {%4,%5,%6,%7}, {%8,%9}, {%0,%1,%2,%3};"
                 : "+f"(c[0]), "+f"(c[1]), "+f"(c[2]), "+f"(c[3])
                 : "r"(a.x), "r"(a.y), "r"(a.z), "r"(a.w), "r"(b.x), "r"(b.y));
}

__device__ __forceinline__ unsigned smem_u32(const void* p) {
    unsigned a;
    asm("{ .reg .u64 t; cvta.to.shared.u64 t, %1; cvt.u32.u64 %0, t; }"
        : "=r"(a) : "l"(p));
    return a;
}

__device__ __forceinline__ void cpa16(unsigned s, const void* g) {
    asm volatile("cp.async.cg.shared.global [%0], [%1], 16;" :: "r"(s), "l"(g));
}

// ---------------------------------------------------------------------------
// Kernel 1: global average pool (float4 loads).
// ---------------------------------------------------------------------------
__global__ void gap_kernel(const float* __restrict__ x) {
    int bc = blockIdx.x;
    const float4* p = (const float4*)(x + (size_t)bc * HW);   // 784 float4
    float s = 0.f;
    for (int i = threadIdx.x; i < HW/4; i += blockDim.x) {
        float4 v = p[i];
        s += (v.x + v.y) + (v.z + v.w);
    }
    __shared__ float red[8];
    for (int off = 16; off > 0; off >>= 1) s += __shfl_down_sync(0xffffffffu, s, off);
    int wid = threadIdx.x >> 5, lid = threadIdx.x & 31;
    if (lid == 0) red[wid] = s;
    __syncthreads();
    if (wid == 0) {
        s = (lid < (blockDim.x >> 5)) ? red[lid] : 0.f;
        for (int off = 4; off > 0; off >>= 1) s += __shfl_down_sync(0xffffffffu, s, off);
        if (lid == 0) g_pooled[bc] = s * (1.f / (float)HW);
    }
}

// ---------------------------------------------------------------------------
// Kernel 2: routing = sigmoid(pooled @ Wr^T + br).
// ---------------------------------------------------------------------------
__global__ void routing_kernel(const float* __restrict__ rw,
                               const float* __restrict__ rb) {
    int t = threadIdx.x;
    if (t >= B*E) return;
    int b = t >> 3, e = t & 7;
    float s = rb[e];
    const float* pp = &g_pooled[b*CIN];
    const float* wp = &rw[e*CIN];
    #pragma unroll 8
    for (int i = 0; i < CIN; i++) s = fmaf(pp[i], wp[i], s);
    g_route[t] = 1.f / (1.f + expf(-s));
}

// ---------------------------------------------------------------------------
// Kernel 3: combine experts -> frag-order fp16 weights, smem-staged.
// Grid (16 cic, 4 cot, 8 z), z = tile*2 + cohalf. 256 threads.
// launch_bounds(256,4) caps regs at 64: R12 measured regs=195 -> 1 CTA/SM
// and the strided writes went latency-bound. 4 CTAs/SM hides them.
// ---------------------------------------------------------------------------
__global__ __launch_bounds__(256, 4)
void combine_kernel(const float* __restrict__ kw) {
    __shared__ float r[B*E];
    __shared__ float s_kw[E * 8 * 144];          // 9216 floats = 36.9 KB
    if (threadIdx.x < B*E) r[threadIdx.x] = g_route[threadIdx.x];

    const int cic    = blockIdx.x;   // 0..15
    const int cot    = blockIdx.y;   // 0..3
    const int tile   = blockIdx.z >> 1;   // 0..3
    const int cohalf = blockIdx.z & 1;    // 0..1
    const int co_base = cot * 64 + tile * 16 + cohalf * 8;

    // ---- Phase A: stage slab (float4: 2304 total, 9 per thread)
    #pragma unroll
    for (int k = 0; k < 9; k++) {
        int f4   = threadIdx.x + 256 * k;        // 0..2303
        int e    = f4 / 288;
        int rem  = f4 - e * 288;
        int grp  = rem / 36;
        int p4   = rem - grp * 36;
        const float4* src = (const float4*)(kw +
            ((size_t)(e * COUT + co_base + grp) * CIN + cic * CI_C) * TAPS) + p4;
        *(float4*)&s_kw[(e * 8 + grp) * 144 + p4 * 4] = *src;
    }
    __syncthreads();

    // ---- Phase B: combine + frag-order writes
    for (int pos = threadIdx.x; pos < 576; pos += 256) {
        int rrhigh = pos & 1;
        int tg     = (pos >> 1) & 3;
        int grp    = (pos >> 3) & 7;
        int tap    = pos >> 6;
        int cie    = 2 * tg + 8 * rrhigh;        // local even ci
        int idx    = tap * 512 + tile * 128 + grp * 16 + tg * 4 + rrhigh * 2 + cohalf;

        float w0[E], w1[E];
        #pragma unroll
        for (int e = 0; e < E; e++) {
            const float* sp = &s_kw[(e * 8 + grp) * 144 + tap];
            w0[e] = sp[cie * TAPS];
            w1[e] = sp[(cie + 1) * TAPS];
        }
        unsigned* dst = g_cwf + ((size_t)cot * NCHUNK + cic) * CHUNK_W + idx;
        #pragma unroll
        for (int b = 0; b < B; b++) {
            float s0 = 0.f, s1 = 0.f;
            #pragma unroll
            for (int e = 0; e < E; e++) {
                float rv = r[b*E + e];
                s0 = fmaf(rv, w0[e], s0);
                s1 = fmaf(rv, w1[e], s1);
            }
            __half2 h = __floats2half2_rn(s0, s1);
            dst[(size_t)b * (4 * NCHUNK * CHUNK_W)] = *(unsigned*)&h;
        }
    }
}

// ---------------------------------------------------------------------------
// Kernel 3b: input prep -> g_xin[b][rq][cic][6*480], zero-padded, fp16,
// slot q = 2*tg+h -> ci pair {2tg+8h, 2tg+8h+1}. Smem transpose.
// Grid (14 rq, 16 cic, 16 b), 256 threads.
// ---------------------------------------------------------------------------
__global__ void prep_kernel(const float* __restrict__ x) {
    const int rq = blockIdx.x, cic = blockIdx.y, b = blockIdx.z;
    const float* xb = x + (size_t)b * CIN * HW;
    __shared__ float s[CI_C * 6 * 61];           // padded stride 61

    // phase A: coalesced global reads
    for (int idx = threadIdx.x; idx < CI_C * 6 * 60; idx += 256) {
        int ci  = idx / 360;
        int rem = idx - ci * 360;
        int row = rem / 60;
        int col = rem - row * 60;
        int gr  = rq * RP + row - 1;
        int gc  = col - 1;
        float v = 0.f;
        if ((unsigned)gr < HH && (unsigned)gc < WW)
            v = xb[(cic * CI_C + ci) * HW + gr * WW + gc];
        s[(ci * 6 + row) * 61 + col] = v;
    }
    __syncthreads();

    // phase B: coalesced interleaved fp16 writes
    unsigned* dst = g_xin + ((size_t)(b * NRQ + rq) * NCHUNK + cic) * CHUNK_IN;
    for (int i = threadIdx.x; i < CHUNK_IN; i += 256) {
        int row = i / ROWU;
        int p   = i - row * ROWU;
        int col = p >> 3;
        int q   = p & 7;
        int ci0 = 2 * (q >> 1) + 8 * (q & 1);
        float f0 = s[((ci0    ) * 6 + row) * 61 + col];
        float f1 = s[((ci0 + 1) * 6 + row) * 61 + col];
        __half2 h = __floats2half2_rn(f0, f1);
        dst[i] = *(unsigned*)&h;
    }
}

// ---------------------------------------------------------------------------
// Kernel 4: fp16 tensor-core implicit conv + BN + SiLU.
// 256 threads = 8 warps: row = wid&3, cohalf = wid>>2 (2 co-tiles each).
// 3 CTAs/SM -> 24 warps/SM (R12 ran 3/SMSP; HMMA issue was the bound).
// ---------------------------------------------------------------------------
__global__ __launch_bounds__(256, 3)
void conv_mma_kernel(const float* __restrict__ bn_gamma,
                     const float* __restrict__ bn_beta,
                     const float* __restrict__ bn_mean,
                     const float* __restrict__ bn_var,
                     float* __restrict__ out) {
    const int rq   = blockIdx.x;
    const int cot  = blockIdx.y;
    const int b    = blockIdx.z;
    const int co0  = cot * CO_T;
    const int row0 = rq * RP;

    const int tid  = threadIdx.x;
    const int lane = tid & 31;
    const int wid  = tid >> 5;        // 0..7
    const int row  = wid & 3;         // output row within CTA
    const int coh  = wid >> 2;        // which pair of co-tiles
    const int tg   = lane & 3;
    const int grp  = lane >> 2;

    __shared__ __align__(16) unsigned s_in[2][CHUNK_IN];
    __shared__ __align__(16) unsigned s_w [2][CHUNK_W];

    const unsigned* gin = g_xin + (size_t)(b * NRQ + rq) * NCHUNK * CHUNK_IN;
    const unsigned* gw  = g_cwf + (size_t)(b * 4 + cot) * NCHUNK * CHUNK_W;

    float acc[2][7][4];
    #pragma unroll
    for (int t = 0; t < 2; t++)
        #pragma unroll
        for (int j = 0; j < 7; j++)
            #pragma unroll
            for (int q = 0; q < 4; q++) acc[t][j][q] = 0.f;

    auto stage = [&](int c, int sb) {
        unsigned din = smem_u32(&s_in[sb][0]);
        unsigned dw  = smem_u32(&s_w[sb][0]);
        const unsigned* src_in = gin + (size_t)c * CHUNK_IN;
        const unsigned* src_w  = gw  + (size_t)c * CHUNK_W;
        #pragma unroll
        for (int k = 0; k < 3; k++) {
            int i = tid + 256 * k;                 // 16B units, 720 total
            if (i < CHUNK_IN / 4)
                cpa16(din + 16u * i, src_in + 4 * i);
        }
        #pragma unroll
        for (int k = 0; k < 5; k++) {
            int i = tid + 256 * k;                 // 1152 total
            if (i < CHUNK_W / 4)
                cpa16(dw + 16u * i, src_w + 4 * i);
        }
    };

    stage(0, 0);
    asm volatile("cp.async.commit_group;");

    for (int c = 0; c < NCHUNK; c++) {
        const int cur = c & 1;
        if (c + 1 < NCHUNK) stage(c + 1, cur ^ 1);
        asm volatile("cp.async.commit_group;");
        asm volatile("cp.async.wait_group 1;");
        __syncthreads();

        #pragma unroll
        for (int kh = 0; kh < 3; kh++) {
            const unsigned* brow = &s_in[cur][(row + kh) * ROWU];
            #pragma unroll
            for (int kw3 = 0; kw3 < 3; kw3++) {
                const int tap = kh * 3 + kw3;
                uint4 a[2];
                #pragma unroll
                for (int t = 0; t < 2; t++)
                    a[t] = *(const uint4*)(&s_w[cur][(tap * 4 + coh * 2 + t) * 128 + lane * 4]);
                uint2 bv[7];
                #pragma unroll
                for (int j = 0; j < 7; j++)
                    bv[j] = *(const uint2*)(&brow[(j * 8 + grp + kw3) * 8 + tg * 2]);
                #pragma unroll
                for (int t = 0; t < 2; t++)
                    #pragma unroll
                    for (int j = 0; j < 7; j++)
                        mma16(acc[t][j], a[t], bv[j]);
            }
        }
        __syncthreads();
    }

    // ---- epilogue: BN + SiLU, float2 stores
    const int orow = row0 + row;
    #pragma unroll
    for (int t = 0; t < 2; t++) {
        const int c1 = co0 + (coh * 2 + t) * 16 + grp;
        const int c2 = c1 + 8;
        const float inv1 = bn_gamma[c1] * rsqrtf(bn_var[c1] + BN_EPS);
        const float sh1  = bn_beta[c1] - bn_mean[c1] * inv1;
        const float inv2 = bn_gamma[c2] * rsqrtf(bn_var[c2] + BN_EPS);
        const float sh2  = bn_beta[c2] - bn_mean[c2] * inv2;
        float* o1 = out + ((size_t)(b * COUT + c1) * HH + orow) * WW;
        float* o2 = out + ((size_t)(b * COUT + c2) * HH + orow) * WW;
        #pragma unroll
        for (int j = 0; j < 7; j++) {
            int col = j * 8 + 2 * tg;
            float y0 = fmaf(acc[t][j][0], inv1, sh1);
            float y1 = fmaf(acc[t][j][1], inv1, sh1);
            float y2 = fmaf(acc[t][j][2], inv2, sh2);
            float y3 = fmaf(acc[t][j][3], inv2, sh2);
            float2 r1 = make_float2(y0 / (1.f + expf(-y0)), y1 / (1.f + expf(-y1)));
            float2 r2 = make_float2(y2 / (1.f + expf(-y2)), y3 / (1.f + expf(-y3)));
            *(float2*)(o1 + col) = r1;
            *(float2*)(o2 + col) = r2;
        }
    }
}

// ---------------------------------------------------------------------------
extern "C" void kernel_launch(void* const* d_in, const int* in_sizes, int n_in,
                              void* d_out, int out_size) {
    const float* x        = (const float*)d_in[0];
    const float* rw       = (const float*)d_in[1];
    const float* rb       = (const float*)d_in[2];
    const float* kw       = (const float*)d_in[3];
    const float* bn_gamma = (const float*)d_in[4];
    const float* bn_beta  = (const float*)d_in[5];
    const float* bn_mean  = (const float*)d_in[6];
    const float* bn_var   = (const float*)d_in[7];
    float* out = (float*)d_out;

    prep_kernel<<<dim3(NRQ, NCHUNK, B), 256>>>(x);
    gap_kernel<<<B*CIN, 256>>>(x);
    routing_kernel<<<1, 128>>>(rw, rb);
    combine_kernel<<<dim3(NCHUNK, 4, 8), 256>>>(kw);
    dim3 grid(NRQ, 4, B);                      // (14, 4, 16)
    conv_mma_kernel<<<grid, 256>>>(bn_gamma, bn_beta, bn_mean, bn_var, out);
}

// round 14
// speedup vs baseline: 1.0459x; 1.0459x over previous
#include <cuda_runtime.h>
#include <cuda_fp16.h>
#include <math.h>
#include <stdint.h>

// Problem constants
#define B    16
#define CIN  256
#define HH   56
#define WW   56
#define E    8
#define COUT 256
#define TAPS 9
#define HW   (HH*WW)                 // 3136
#define BN_EPS 1e-5f

// Conv tiling (fp16, K=16 per mma)
#define CO_T 64        // co per CTA
#define RP   4         // output rows per CTA (= warps)
#define CI_C 16        // ci chunk (== mma K)
#define NCHUNK 16      // CIN / CI_C
#define NRQ    14      // HH / RP
#define ROWU 480       // uint32 per patch row (60 cols * 8 slots)
#define CHUNK_IN 2880  // 6*480 uint32 per input chunk  (11520 B)
#define CHUNK_W  4608  // 9*4*32*4 uint32 per weight chunk (18432 B)

// Device scratch (allocation-free rule)
__device__ float g_pooled[B*CIN];
__device__ float g_route[B*E];
// frag-order fp16 weights: [b][cot(4)][cic(16)][4608 u32]
__device__ unsigned g_cwf[(size_t)B*4*NCHUNK*CHUNK_W];
// interleaved fp16 input patches: [b][rq(14)][cic(16)][2880 u32]
__device__ unsigned g_xin[(size_t)B*NRQ*NCHUNK*CHUNK_IN];

// ---------------------------------------------------------------------------
__device__ __forceinline__ void mma16(float* c, uint4 a, uint2 b) {
    asm volatile("mma.sync.aligned.m16n8k16.row.col.f32.f16.f16.f32 "
                 "{%0,%1,%2,%3}, {%4,%5,%6,%7}, {%8,%9}, {%0,%1,%2,%3};"
                 : "+f"(c[0]), "+f"(c[1]), "+f"(c[2]), "+f"(c[3])
                 : "r"(a.x), "r"(a.y), "r"(a.z), "r"(a.w), "r"(b.x), "r"(b.y));
}

__device__ __forceinline__ unsigned smem_u32(const void* p) {
    unsigned a;
    asm("{ .reg .u64 t; cvta.to.shared.u64 t, %1; cvt.u32.u64 %0, t; }"
        : "=r"(a) : "l"(p));
    return a;
}

__device__ __forceinline__ void cpa16(unsigned s, const void* g) {
    asm volatile("cp.async.cg.shared.global [%0], [%1], 16;" :: "r"(s), "l"(g));
}

// ---------------------------------------------------------------------------
// Kernel 1: global average pool (float4 loads).
// ---------------------------------------------------------------------------
__global__ void gap_kernel(const float* __restrict__ x) {
    int bc = blockIdx.x;
    const float4* p = (const float4*)(x + (size_t)bc * HW);   // 784 float4
    float s = 0.f;
    for (int i = threadIdx.x; i < HW/4; i += blockDim.x) {
        float4 v = p[i];
        s += (v.x + v.y) + (v.z + v.w);
    }
    __shared__ float red[8];
    for (int off = 16; off > 0; off >>= 1) s += __shfl_down_sync(0xffffffffu, s, off);
    int wid = threadIdx.x >> 5, lid = threadIdx.x & 31;
    if (lid == 0) red[wid] = s;
    __syncthreads();
    if (wid == 0) {
        s = (lid < (blockDim.x >> 5)) ? red[lid] : 0.f;
        for (int off = 4; off > 0; off >>= 1) s += __shfl_down_sync(0xffffffffu, s, off);
        if (lid == 0) g_pooled[bc] = s * (1.f / (float)HW);
    }
}

// ---------------------------------------------------------------------------
// Kernel 2: routing = sigmoid(pooled @ Wr^T + br).
// ---------------------------------------------------------------------------
__global__ void routing_kernel(const float* __restrict__ rw,
                               const float* __restrict__ rb) {
    int t = threadIdx.x;
    if (t >= B*E) return;
    int b = t >> 3, e = t & 7;
    float s = rb[e];
    const float* pp = &g_pooled[b*CIN];
    const float* wp = &rw[e*CIN];
    #pragma unroll 8
    for (int i = 0; i < CIN; i++) s = fmaf(pp[i], wp[i], s);
    g_route[t] = 1.f / (1.f + expf(-s));
}

// ---------------------------------------------------------------------------
// Kernel 3: combine experts -> frag-order fp16 weights, smem-staged, 16-co
// blocks so writes are contiguous uint4.
// Grid (16 cic, 4 cot, 4 tile), 256 threads, 73.7 KB dynamic smem.
// Block set: co = cot*64 + tile*16 + [0..15], ci = cic*16 + [0..15], taps 0..8.
// Output u32 at idx = tap*512 + tile*128 + grp*16 + tg*4 + rrhigh*2 + cohalf,
//   value = half2(cw[co(cohalf,grp)][ci(rrhigh,tg)], cw[co][ci+1])
//   with co = base + cohalf*8 + grp, ci = 2*tg + 8*rrhigh.
// Low 2 bits (rrhigh,cohalf) now live IN one thread -> one uint4 store.
// ---------------------------------------------------------------------------
__global__ void combine_kernel(const float* __restrict__ kw) {
    extern __shared__ float s_kw[];              // [e][co16][144] = 18432 floats
    __shared__ float r[B*E];
    if (threadIdx.x < B*E) r[threadIdx.x] = g_route[threadIdx.x];

    const int cic  = blockIdx.x;   // 0..15
    const int cot  = blockIdx.y;   // 0..3
    const int tile = blockIdx.z;   // 0..3
    const int co_base = cot * 64 + tile * 16;

    // ---- Phase A: coalesced float4 stage of the 8e x 16co x 144 slab
    #pragma unroll
    for (int k = 0; k < 18; k++) {
        int f4  = threadIdx.x + 256 * k;         // 0..4607
        int e   = f4 / 576;
        int rem = f4 - e * 576;
        int co  = rem / 36;
        int p4  = rem - co * 36;
        const float4* src = (const float4*)(kw +
            ((size_t)(e * COUT + co_base + co) * CIN + cic * CI_C) * TAPS) + p4;
        *(float4*)&s_kw[(e * 16 + co) * 144 + p4 * 4] = *src;
    }
    __syncthreads();

    // ---- Phase B: combine + contiguous uint4 frag writes
    for (int pos = threadIdx.x; pos < 288; pos += 256) {
        // pos = tap*32 + grp*4 + tg
        int tg  = pos & 3;
        int grp = (pos >> 2) & 7;
        int tap = pos >> 5;

        // weights for the 4 uint4 components: k = rrhigh*2 + cohalf
        float w0[4][E], w1[4][E];
        #pragma unroll
        for (int k4 = 0; k4 < 4; k4++) {
            int cohalf = k4 & 1, rrhigh = k4 >> 1;
            int co_l = cohalf * 8 + grp;
            int ci_l = 2 * tg + 8 * rrhigh;
            #pragma unroll
            for (int e = 0; e < E; e++) {
                const float* sp = &s_kw[(e * 16 + co_l) * 144 + ci_l * TAPS + tap];
                w0[k4][e] = sp[0];
                w1[k4][e] = sp[TAPS];
            }
        }

        size_t idx4 = (size_t)tap * 128 + tile * 32 + grp * 4 + tg;  // uint4 units
        uint4* dst = (uint4*)g_cwf + ((size_t)cot * NCHUNK + cic) * (CHUNK_W/4) + idx4;
        const size_t bstride4 = (size_t)4 * NCHUNK * CHUNK_W / 4;
        #pragma unroll
        for (int b = 0; b < B; b++) {
            uint4 v;
            unsigned* vp = (unsigned*)&v;
            #pragma unroll
            for (int k4 = 0; k4 < 4; k4++) {
                float s0 = 0.f, s1 = 0.f;
                #pragma unroll
                for (int e = 0; e < E; e++) {
                    float rv = r[b*E + e];
                    s0 = fmaf(rv, w0[k4][e], s0);
                    s1 = fmaf(rv, w1[k4][e], s1);
                }
                __half2 h = __floats2half2_rn(s0, s1);
                vp[k4] = *(unsigned*)&h;
            }
            dst[(size_t)b * bstride4] = v;
        }
    }
}

// ---------------------------------------------------------------------------
// Kernel 3b: input prep -> g_xin[b][rq][cic][6*480], zero-padded, fp16,
// slot q = 2*tg+h -> ci pair {2tg+8h, 2tg+8h+1}. Smem transpose.
// Grid (14 rq, 16 cic, 16 b), 256 threads.
// ---------------------------------------------------------------------------
__global__ void prep_kernel(const float* __restrict__ x) {
    const int rq = blockIdx.x, cic = blockIdx.y, b = blockIdx.z;
    const float* xb = x + (size_t)b * CIN * HW;
    __shared__ float s[CI_C * 6 * 61];           // padded stride 61

    // phase A: coalesced global reads
    for (int idx = threadIdx.x; idx < CI_C * 6 * 60; idx += 256) {
        int ci  = idx / 360;
        int rem = idx - ci * 360;
        int row = rem / 60;
        int col = rem - row * 60;
        int gr  = rq * RP + row - 1;
        int gc  = col - 1;
        float v = 0.f;
        if ((unsigned)gr < HH && (unsigned)gc < WW)
            v = xb[(cic * CI_C + ci) * HW + gr * WW + gc];
        s[(ci * 6 + row) * 61 + col] = v;
    }
    __syncthreads();

    // phase B: coalesced interleaved fp16 writes
    unsigned* dst = g_xin + ((size_t)(b * NRQ + rq) * NCHUNK + cic) * CHUNK_IN;
    for (int i = threadIdx.x; i < CHUNK_IN; i += 256) {
        int row = i / ROWU;
        int p   = i - row * ROWU;
        int col = p >> 3;
        int q   = p & 7;
        int ci0 = 2 * (q >> 1) + 8 * (q & 1);
        float f0 = s[((ci0    ) * 6 + row) * 61 + col];
        float f1 = s[((ci0 + 1) * 6 + row) * 61 + col];
        __half2 h = __floats2half2_rn(f0, f1);
        dst[i] = *(unsigned*)&h;
    }
}

// ---------------------------------------------------------------------------
// Kernel 4: fp16 tensor-core implicit conv + BN + SiLU. (R12 version: 128
// threads/4 warps — R13's 256-thread split duplicated B-frag LDS and lost.)
// ---------------------------------------------------------------------------
__global__ __launch_bounds__(128, 3)
void conv_mma_kernel(const float* __restrict__ bn_gamma,
                     const float* __restrict__ bn_beta,
                     const float* __restrict__ bn_mean,
                     const float* __restrict__ bn_var,
                     float* __restrict__ out) {
    const int rq   = blockIdx.x;
    const int cot  = blockIdx.y;
    const int b    = blockIdx.z;
    const int co0  = cot * CO_T;
    const int row0 = rq * RP;

    const int tid  = threadIdx.x;
    const int lane = tid & 31;
    const int wid  = tid >> 5;
    const int tg   = lane & 3;
    const int grp  = lane >> 2;

    __shared__ __align__(16) unsigned s_in[2][CHUNK_IN];
    __shared__ __align__(16) unsigned s_w [2][CHUNK_W];

    const unsigned* gin = g_xin + (size_t)(b * NRQ + rq) * NCHUNK * CHUNK_IN;
    const unsigned* gw  = g_cwf + (size_t)(b * 4 + cot) * NCHUNK * CHUNK_W;

    float acc[4][7][4];
    #pragma unroll
    for (int t = 0; t < 4; t++)
        #pragma unroll
        for (int j = 0; j < 7; j++)
            #pragma unroll
            for (int q = 0; q < 4; q++) acc[t][j][q] = 0.f;

    auto stage = [&](int c, int sb) {
        unsigned din = smem_u32(&s_in[sb][0]);
        unsigned dw  = smem_u32(&s_w[sb][0]);
        const unsigned* src_in = gin + (size_t)c * CHUNK_IN;
        const unsigned* src_w  = gw  + (size_t)c * CHUNK_W;
        #pragma unroll
        for (int k = 0; k < 6; k++) {
            int i = tid + 128 * k;                 // 16B units, 720 total
            if (i < CHUNK_IN / 4)
                cpa16(din + 16u * i, src_in + 4 * i);
        }
        #pragma unroll
        for (int k = 0; k < 9; k++) {
            int i = tid + 128 * k;                 // 1152 total
            cpa16(dw + 16u * i, src_w + 4 * i);
        }
    };

    stage(0, 0);
    asm volatile("cp.async.commit_group;");

    for (int c = 0; c < NCHUNK; c++) {
        const int cur = c & 1;
        if (c + 1 < NCHUNK) stage(c + 1, cur ^ 1);
        asm volatile("cp.async.commit_group;");
        asm volatile("cp.async.wait_group 1;");
        __syncthreads();

        #pragma unroll
        for (int kh = 0; kh < 3; kh++) {
            const unsigned* brow = &s_in[cur][(wid + kh) * ROWU];
            #pragma unroll
            for (int kw3 = 0; kw3 < 3; kw3++) {
                const int tap = kh * 3 + kw3;
                uint4 a[4];
                #pragma unroll
                for (int t = 0; t < 4; t++)
                    a[t] = *(const uint4*)(&s_w[cur][(tap * 4 + t) * 128 + lane * 4]);
                uint2 bv[7];
                #pragma unroll
                for (int j = 0; j < 7; j++)
                    bv[j] = *(const uint2*)(&brow[(j * 8 + grp + kw3) * 8 + tg * 2]);
                #pragma unroll
                for (int t = 0; t < 4; t++)
                    #pragma unroll
                    for (int j = 0; j < 7; j++)
                        mma16(acc[t][j], a[t], bv[j]);
            }
        }
        __syncthreads();
    }

    // ---- epilogue: BN + SiLU, float2 stores
    const int orow = row0 + wid;
    #pragma unroll
    for (int t = 0; t < 4; t++) {
        const int c1 = co0 + t * 16 + grp;
        const int c2 = c1 + 8;
        const float inv1 = bn_gamma[c1] * rsqrtf(bn_var[c1] + BN_EPS);
        const float sh1  = bn_beta[c1] - bn_mean[c1] * inv1;
        const float inv2 = bn_gamma[c2] * rsqrtf(bn_var[c2] + BN_EPS);
        const float sh2  = bn_beta[c2] - bn_mean[c2] * inv2;
        float* o1 = out + ((size_t)(b * COUT + c1) * HH + orow) * WW;
        float* o2 = out + ((size_t)(b * COUT + c2) * HH + orow) * WW;
        #pragma unroll
        for (int j = 0; j < 7; j++) {
            int col = j * 8 + 2 * tg;
            float y0 = fmaf(acc[t][j][0], inv1, sh1);
            float y1 = fmaf(acc[t][j][1], inv1, sh1);
            float y2 = fmaf(acc[t][j][2], inv2, sh2);
            float y3 = fmaf(acc[t][j][3], inv2, sh2);
            float2 r1 = make_float2(y0 / (1.f + expf(-y0)), y1 / (1.f + expf(-y1)));
            float2 r2 = make_float2(y2 / (1.f + expf(-y2)), y3 / (1.f + expf(-y3)));
            *(float2*)(o1 + col) = r1;
            *(float2*)(o2 + col) = r2;
        }
    }
}

// ---------------------------------------------------------------------------
extern "C" void kernel_launch(void* const* d_in, const int* in_sizes, int n_in,
                              void* d_out, int out_size) {
    const float* x        = (const float*)d_in[0];
    const float* rw       = (const float*)d_in[1];
    const float* rb       = (const float*)d_in[2];
    const float* kw       = (const float*)d_in[3];
    const float* bn_gamma = (const float*)d_in[4];
    const float* bn_beta  = (const float*)d_in[5];
    const float* bn_mean  = (const float*)d_in[6];
    const float* bn_var   = (const float*)d_in[7];
    float* out = (float*)d_out;

    const int combine_smem = E * 16 * 144 * (int)sizeof(float);   // 73728 B
    cudaFuncSetAttribute(combine_kernel,
                         cudaFuncAttributeMaxDynamicSharedMemorySize, combine_smem);

    prep_kernel<<<dim3(NRQ, NCHUNK, B), 256>>>(x);
    gap_kernel<<<B*CIN, 256>>>(x);
    routing_kernel<<<1, 128>>>(rw, rb);
    combine_kernel<<<dim3(NCHUNK, 4, 4), 256, combine_smem>>>(kw);
    dim3 grid(NRQ, 4, B);                      // (14, 4, 16)
    conv_mma_kernel<<<grid, 128>>>(bn_gamma, bn_beta, bn_mean, bn_var, out);
}

// round 15
// speedup vs baseline: 1.0492x; 1.0032x over previous
#include <cuda_runtime.h>
#include <cuda_fp16.h>
#include <math.h>
#include <stdint.h>

// Problem constants
#define B    16
#define CIN  256
#define HH   56
#define WW   56
#define E    8
#define COUT 256
#define TAPS 9
#define HW   (HH*WW)                 // 3136
#define BN_EPS 1e-5f

// Conv tiling (fp16, K=16 per mma)
#define CO_T 64        // co per CTA
#define RP   4         // output rows per CTA (= warps)
#define CI_C 16        // ci chunk (== mma K)
#define NCHUNK 16      // CIN / CI_C
#define NRQ    14      // HH / RP
#define ROWU 480       // uint32 per patch row (60 cols * 8 slots)
#define CHUNK_IN 2880  // 6*480 uint32 per input chunk  (11520 B)
#define CHUNK_W  4608  // 9*4*32*4 uint32 per weight chunk (18432 B)

// Device scratch (allocation-free rule)
__device__ float g_pooled[B*CIN];
__device__ float g_route[B*E];
// frag-order fp16 weights: [b][cot(4)][cic(16)][4608 u32]
__device__ unsigned g_cwf[(size_t)B*4*NCHUNK*CHUNK_W];
// interleaved fp16 input patches: [b][rq(14)][cic(16)][2880 u32]
__device__ unsigned g_xin[(size_t)B*NRQ*NCHUNK*CHUNK_IN];

// ---------------------------------------------------------------------------
__device__ __forceinline__ void mma16(float* c, uint4 a, uint2 b) {
    asm volatile("mma.sync.aligned.m16n8k16.row.col.f32.f16.f16.f32 "
                 "{%0,%1,%2,%3}, {%4,%5,%6,%7}, {%8,%9}, {%0,%1,%2,%3};"
                 : "+f"(c[0]), "+f"(c[1]), "+f"(c[2]), "+f"(c[3])
                 : "r"(a.x), "r"(a.y), "r"(a.z), "r"(a.w), "r"(b.x), "r"(b.y));
}

__device__ __forceinline__ unsigned smem_u32(const void* p) {
    unsigned a;
    asm("{ .reg .u64 t; cvta.to.shared.u64 t, %1; cvt.u32.u64 %0, t; }"
        : "=r"(a) : "l"(p));
    return a;
}

__device__ __forceinline__ void cpa16(unsigned s, const void* g) {
    asm volatile("cp.async.cg.shared.global [%0], [%1], 16;" :: "r"(s), "l"(g));
}

// ---------------------------------------------------------------------------
// Kernel 1: global average pool (float4 loads).
// ---------------------------------------------------------------------------
__global__ void gap_kernel(const float* __restrict__ x) {
    int bc = blockIdx.x;
    const float4* p = (const float4*)(x + (size_t)bc * HW);   // 784 float4
    float s = 0.f;
    for (int i = threadIdx.x; i < HW/4; i += blockDim.x) {
        float4 v = p[i];
        s += (v.x + v.y) + (v.z + v.w);
    }
    __shared__ float red[8];
    for (int off = 16; off > 0; off >>= 1) s += __shfl_down_sync(0xffffffffu, s, off);
    int wid = threadIdx.x >> 5, lid = threadIdx.x & 31;
    if (lid == 0) red[wid] = s;
    __syncthreads();
    if (wid == 0) {
        s = (lid < (blockDim.x >> 5)) ? red[lid] : 0.f;
        for (int off = 4; off > 0; off >>= 1) s += __shfl_down_sync(0xffffffffu, s, off);
        if (lid == 0) g_pooled[bc] = s * (1.f / (float)HW);
    }
}

// ---------------------------------------------------------------------------
// Kernel 2: routing = sigmoid(pooled @ Wr^T + br).
// ---------------------------------------------------------------------------
__global__ void routing_kernel(const float* __restrict__ rw,
                               const float* __restrict__ rb) {
    int t = threadIdx.x;
    if (t >= B*E) return;
    int b = t >> 3, e = t & 7;
    float s = rb[e];
    const float* pp = &g_pooled[b*CIN];
    const float* wp = &rw[e*CIN];
    #pragma unroll 8
    for (int i = 0; i < CIN; i++) s = fmaf(pp[i], wp[i], s);
    g_route[t] = 1.f / (1.f + expf(-s));
}

// ---------------------------------------------------------------------------
// Kernel 3: combine experts -> frag-order fp16 weights, smem-staged, 16-co
// blocks, contiguous uint4 writes. b-loop split in half across blockIdx.z
// (R14 was grid-limited at 256 blocks / occ 10.9%).
// Grid (16 cic, 4 cot, 8 z) with z = tile*2 + bh. 256 threads, 73.7 KB smem.
// ---------------------------------------------------------------------------
__global__ void combine_kernel(const float* __restrict__ kw) {
    extern __shared__ float s_kw[];              // [e][co16][144] = 18432 floats
    __shared__ float r[B*E];
    if (threadIdx.x < B*E) r[threadIdx.x] = g_route[threadIdx.x];

    const int cic  = blockIdx.x;        // 0..15
    const int cot  = blockIdx.y;        // 0..3
    const int tile = blockIdx.z >> 1;   // 0..3
    const int bh   = blockIdx.z & 1;    // 0..1  (which half of the batch)
    const int co_base = cot * 64 + tile * 16;

    // ---- Phase A: coalesced float4 stage of the 8e x 16co x 144 slab
    #pragma unroll
    for (int k = 0; k < 18; k++) {
        int f4  = threadIdx.x + 256 * k;         // 0..4607
        int e   = f4 / 576;
        int rem = f4 - e * 576;
        int co  = rem / 36;
        int p4  = rem - co * 36;
        const float4* src = (const float4*)(kw +
            ((size_t)(e * COUT + co_base + co) * CIN + cic * CI_C) * TAPS) + p4;
        *(float4*)&s_kw[(e * 16 + co) * 144 + p4 * 4] = *src;
    }
    __syncthreads();

    // ---- Phase B: combine + contiguous uint4 frag writes
    for (int pos = threadIdx.x; pos < 288; pos += 256) {
        int tg  = pos & 3;
        int grp = (pos >> 2) & 7;
        int tap = pos >> 5;

        float w0[4][E], w1[4][E];
        #pragma unroll
        for (int k4 = 0; k4 < 4; k4++) {
            int cohalf = k4 & 1, rrhigh = k4 >> 1;
            int co_l = cohalf * 8 + grp;
            int ci_l = 2 * tg + 8 * rrhigh;
            #pragma unroll
            for (int e = 0; e < E; e++) {
                const float* sp = &s_kw[(e * 16 + co_l) * 144 + ci_l * TAPS + tap];
                w0[k4][e] = sp[0];
                w1[k4][e] = sp[TAPS];
            }
        }

        size_t idx4 = (size_t)tap * 128 + tile * 32 + grp * 4 + tg;  // uint4 units
        uint4* dst = (uint4*)g_cwf + ((size_t)cot * NCHUNK + cic) * (CHUNK_W/4) + idx4;
        const size_t bstride4 = (size_t)4 * NCHUNK * CHUNK_W / 4;
        #pragma unroll
        for (int bb = 0; bb < 8; bb++) {
            int b = bh * 8 + bb;
            uint4 v;
            unsigned* vp = (unsigned*)&v;
            #pragma unroll
            for (int k4 = 0; k4 < 4; k4++) {
                float s0 = 0.f, s1 = 0.f;
                #pragma unroll
                for (int e = 0; e < E; e++) {
                    float rv = r[b*E + e];
                    s0 = fmaf(rv, w0[k4][e], s0);
                    s1 = fmaf(rv, w1[k4][e], s1);
                }
                __half2 h = __floats2half2_rn(s0, s1);
                vp[k4] = *(unsigned*)&h;
            }
            dst[(size_t)b * bstride4] = v;
        }
    }
}

// ---------------------------------------------------------------------------
// Kernel 3b: input prep -> g_xin[b][rq][cic][6*480], zero-padded, fp16,
// slot q = 2*tg+h -> ci pair {2tg+8h, 2tg+8h+1}. Smem transpose.
// Grid (14 rq, 16 cic, 16 b), 256 threads.
// ---------------------------------------------------------------------------
__global__ void prep_kernel(const float* __restrict__ x) {
    const int rq = blockIdx.x, cic = blockIdx.y, b = blockIdx.z;
    const float* xb = x + (size_t)b * CIN * HW;
    __shared__ float s[CI_C * 6 * 61];           // padded stride 61

    // phase A: coalesced global reads
    for (int idx = threadIdx.x; idx < CI_C * 6 * 60; idx += 256) {
        int ci  = idx / 360;
        int rem = idx - ci * 360;
        int row = rem / 60;
        int col = rem - row * 60;
        int gr  = rq * RP + row - 1;
        int gc  = col - 1;
        float v = 0.f;
        if ((unsigned)gr < HH && (unsigned)gc < WW)
            v = xb[(cic * CI_C + ci) * HW + gr * WW + gc];
        s[(ci * 6 + row) * 61 + col] = v;
    }
    __syncthreads();

    // phase B: coalesced interleaved fp16 writes
    unsigned* dst = g_xin + ((size_t)(b * NRQ + rq) * NCHUNK + cic) * CHUNK_IN;
    for (int i = threadIdx.x; i < CHUNK_IN; i += 256) {
        int row = i / ROWU;
        int p   = i - row * ROWU;
        int col = p >> 3;
        int q   = p & 7;
        int ci0 = 2 * (q >> 1) + 8 * (q & 1);
        float f0 = s[((ci0    ) * 6 + row) * 61 + col];
        float f1 = s[((ci0 + 1) * 6 + row) * 61 + col];
        __half2 h = __floats2half2_rn(f0, f1);
        dst[i] = *(unsigned*)&h;
    }
}

// ---------------------------------------------------------------------------
// Kernel 4: fp16 tensor-core implicit conv + BN + SiLU. (unchanged R12/R14)
// ---------------------------------------------------------------------------
__global__ __launch_bounds__(128, 3)
void conv_mma_kernel(const float* __restrict__ bn_gamma,
                     const float* __restrict__ bn_beta,
                     const float* __restrict__ bn_mean,
                     const float* __restrict__ bn_var,
                     float* __restrict__ out) {
    const int rq   = blockIdx.x;
    const int cot  = blockIdx.y;
    const int b    = blockIdx.z;
    const int co0  = cot * CO_T;
    const int row0 = rq * RP;

    const int tid  = threadIdx.x;
    const int lane = tid & 31;
    const int wid  = tid >> 5;
    const int tg   = lane & 3;
    const int grp  = lane >> 2;

    __shared__ __align__(16) unsigned s_in[2][CHUNK_IN];
    __shared__ __align__(16) unsigned s_w [2][CHUNK_W];

    const unsigned* gin = g_xin + (size_t)(b * NRQ + rq) * NCHUNK * CHUNK_IN;
    const unsigned* gw  = g_cwf + (size_t)(b * 4 + cot) * NCHUNK * CHUNK_W;

    float acc[4][7][4];
    #pragma unroll
    for (int t = 0; t < 4; t++)
        #pragma unroll
        for (int j = 0; j < 7; j++)
            #pragma unroll
            for (int q = 0; q < 4; q++) acc[t][j][q] = 0.f;

    auto stage = [&](int c, int sb) {
        unsigned din = smem_u32(&s_in[sb][0]);
        unsigned dw  = smem_u32(&s_w[sb][0]);
        const unsigned* src_in = gin + (size_t)c * CHUNK_IN;
        const unsigned* src_w  = gw  + (size_t)c * CHUNK_W;
        #pragma unroll
        for (int k = 0; k < 6; k++) {
            int i = tid + 128 * k;                 // 16B units, 720 total
            if (i < CHUNK_IN / 4)
                cpa16(din + 16u * i, src_in + 4 * i);
        }
        #pragma unroll
        for (int k = 0; k < 9; k++) {
            int i = tid + 128 * k;                 // 1152 total
            cpa16(dw + 16u * i, src_w + 4 * i);
        }
    };

    stage(0, 0);
    asm volatile("cp.async.commit_group;");

    for (int c = 0; c < NCHUNK; c++) {
        const int cur = c & 1;
        if (c + 1 < NCHUNK) stage(c + 1, cur ^ 1);
        asm volatile("cp.async.commit_group;");
        asm volatile("cp.async.wait_group 1;");
        __syncthreads();

        #pragma unroll
        for (int kh = 0; kh < 3; kh++) {
            const unsigned* brow = &s_in[cur][(wid + kh) * ROWU];
            #pragma unroll
            for (int kw3 = 0; kw3 < 3; kw3++) {
                const int tap = kh * 3 + kw3;
                uint4 a[4];
                #pragma unroll
                for (int t = 0; t < 4; t++)
                    a[t] = *(const uint4*)(&s_w[cur][(tap * 4 + t) * 128 + lane * 4]);
                uint2 bv[7];
                #pragma unroll
                for (int j = 0; j < 7; j++)
                    bv[j] = *(const uint2*)(&brow[(j * 8 + grp + kw3) * 8 + tg * 2]);
                #pragma unroll
                for (int t = 0; t < 4; t++)
                    #pragma unroll
                    for (int j = 0; j < 7; j++)
                        mma16(acc[t][j], a[t], bv[j]);
            }
        }
        __syncthreads();
    }

    // ---- epilogue: BN + SiLU, float2 stores
    const int orow = row0 + wid;
    #pragma unroll
    for (int t = 0; t < 4; t++) {
        const int c1 = co0 + t * 16 + grp;
        const int c2 = c1 + 8;
        const float inv1 = bn_gamma[c1] * rsqrtf(bn_var[c1] + BN_EPS);
        const float sh1  = bn_beta[c1] - bn_mean[c1] * inv1;
        const float inv2 = bn_gamma[c2] * rsqrtf(bn_var[c2] + BN_EPS);
        const float sh2  = bn_beta[c2] - bn_mean[c2] * inv2;
        float* o1 = out + ((size_t)(b * COUT + c1) * HH + orow) * WW;
        float* o2 = out + ((size_t)(b * COUT + c2) * HH + orow) * WW;
        #pragma unroll
        for (int j = 0; j < 7; j++) {
            int col = j * 8 + 2 * tg;
            float y0 = fmaf(acc[t][j][0], inv1, sh1);
            float y1 = fmaf(acc[t][j][1], inv1, sh1);
            float y2 = fmaf(acc[t][j][2], inv2, sh2);
            float y3 = fmaf(acc[t][j][3], inv2, sh2);
            float2 r1 = make_float2(y0 / (1.f + expf(-y0)), y1 / (1.f + expf(-y1)));
            float2 r2 = make_float2(y2 / (1.f + expf(-y2)), y3 / (1.f + expf(-y3)));
            *(float2*)(o1 + col) = r1;
            *(float2*)(o2 + col) = r2;
        }
    }
}

// ---------------------------------------------------------------------------
// Launch: fork prep onto a side stream so it overlaps gap->routing->combine.
// Streams/events are created once on the first (uncaptured) call; during
// graph capture the event record/wait pairs become graph edges.
// ---------------------------------------------------------------------------
extern "C" void kernel_launch(void* const* d_in, const int* in_sizes, int n_in,
                              void* d_out, int out_size) {
    const float* x        = (const float*)d_in[0];
    const float* rw       = (const float*)d_in[1];
    const float* rb       = (const float*)d_in[2];
    const float* kw       = (const float*)d_in[3];
    const float* bn_gamma = (const float*)d_in[4];
    const float* bn_beta  = (const float*)d_in[5];
    const float* bn_mean  = (const float*)d_in[6];
    const float* bn_var   = (const float*)d_in[7];
    float* out = (float*)d_out;

    static cudaStream_t s2 = nullptr;
    static cudaEvent_t evFork = nullptr, evJoin = nullptr;
    if (s2 == nullptr) {
        cudaStreamCreateWithFlags(&s2, cudaStreamNonBlocking);
        cudaEventCreateWithFlags(&evFork, cudaEventDisableTiming);
        cudaEventCreateWithFlags(&evJoin, cudaEventDisableTiming);
    }

    const int combine_smem = E * 16 * 144 * (int)sizeof(float);   // 73728 B
    cudaFuncSetAttribute(combine_kernel,
                         cudaFuncAttributeMaxDynamicSharedMemorySize, combine_smem);

    // fork: prep runs on s2 concurrent with gap -> routing -> combine
    cudaEventRecord(evFork, 0);
    cudaStreamWaitEvent(s2, evFork, 0);
    prep_kernel<<<dim3(NRQ, NCHUNK, B), 256, 0, s2>>>(x);

    gap_kernel<<<B*CIN, 256>>>(x);
    routing_kernel<<<1, 128>>>(rw, rb);
    combine_kernel<<<dim3(NCHUNK, 4, 8), 256, combine_smem>>>(kw);

    // join: conv needs both prep (s2) and combine (default stream)
    cudaEventRecord(evJoin, s2);
    cudaStreamWaitEvent(0, evJoin, 0);
    dim3 grid(NRQ, 4, B);                      // (14, 4, 16)
    conv_mma_kernel<<<grid, 128>>>(bn_gamma, bn_beta, bn_mean, bn_var, out);
}

// round 17
// speedup vs baseline: 1.0615x; 1.0116x over previous
#include <cuda_runtime.h>
#include <cuda_fp16.h>
#include <math.h>
#include <stdint.h>

// Problem constants
#define B    16
#define CIN  256
#define HH   56
#define WW   56
#define E    8
#define COUT 256
#define TAPS 9
#define HW   (HH*WW)                 // 3136
#define BN_EPS 1e-5f

// Conv tiling (fp16, K=16 per mma)
#define CO_T 64        // co per CTA
#define RP   4         // output rows per CTA (= warps)
#define CI_C 16        // ci chunk (== mma K)
#define NCHUNK 16      // CIN / CI_C
#define NRQ    14      // HH / RP
#define ROWU 480       // uint32 per patch row (60 cols * 8 slots)
#define CHUNK_IN 2880  // 6*480 uint32 per input chunk  (11520 B)
#define CHUNK_W  4608  // 9*4*32*4 uint32 per weight chunk (18432 B)
#define NITEMS (NRQ * 4 * B)   // 896 work items

// Device scratch (allocation-free rule)
__device__ float g_pooled[B*CIN];
__device__ float g_route[B*E];
__device__ unsigned g_work;          // persistent-conv work counter
// frag-order fp16 weights: [b][cot(4)][cic(16)][4608 u32]
__device__ unsigned g_cwf[(size_t)B*4*NCHUNK*CHUNK_W];
// interleaved fp16 input patches: [b][rq(14)][cic(16)][2880 u32]
__device__ unsigned g_xin[(size_t)B*NRQ*NCHUNK*CHUNK_IN];

// ---------------------------------------------------------------------------
__device__ __forceinline__ void mma16(float* c, uint4 a, uint2 b) {
    asm volatile("mma.sync.aligned.m16n8k16.row.col.f32.f16.f16.f32 "
                 "{%0,%1,%2,%3}, {%4,%5,%6,%7}, {%8,%9}, {%0,%1,%2,%3};"
                 : "+f"(c[0]), "+f"(c[1]), "+f"(c[2]), "+f"(c[3])
                 : "r"(a.x), "r"(a.y), "r"(a.z), "r"(a.w), "r"(b.x), "r"(b.y));
}

__device__ __forceinline__ unsigned smem_u32(const void* p) {
    unsigned a;
    asm("{ .reg .u64 t; cvta.to.shared.u64 t, %1; cvt.u32.u64 %0, t; }"
        : "=r"(a) : "l"(p));
    return a;
}

__device__ __forceinline__ void cpa16(unsigned s, const void* g) {
    asm volatile("cp.async.cg.shared.global [%0], [%1], 16;" :: "r"(s), "l"(g));
}

// ---------------------------------------------------------------------------
// Kernel 1: global average pool (float4 loads). Also resets the work counter.
// ---------------------------------------------------------------------------
__global__ void gap_kernel(const float* __restrict__ x) {
    if (blockIdx.x == 0 && threadIdx.x == 0) g_work = 0u;
    int bc = blockIdx.x;
    const float4* p = (const float4*)(x + (size_t)bc * HW);   // 784 float4
    float s = 0.f;
    for (int i = threadIdx.x; i < HW/4; i += blockDim.x) {
        float4 v = p[i];
        s += (v.x + v.y) + (v.z + v.w);
    }
    __shared__ float red[8];
    for (int off = 16; off > 0; off >>= 1) s += __shfl_down_sync(0xffffffffu, s, off);
    int wid = threadIdx.x >> 5, lid = threadIdx.x & 31;
    if (lid == 0) red[wid] = s;
    __syncthreads();
    if (wid == 0) {
        s = (lid < (blockDim.x >> 5)) ? red[lid] : 0.f;
        for (int off = 4; off > 0; off >>= 1) s += __shfl_down_sync(0xffffffffu, s, off);
        if (lid == 0) g_pooled[bc] = s * (1.f / (float)HW);
    }
}

// ---------------------------------------------------------------------------
// Kernel 2: routing = sigmoid(pooled @ Wr^T + br).
// ---------------------------------------------------------------------------
__global__ void routing_kernel(const float* __restrict__ rw,
                               const float* __restrict__ rb) {
    int t = threadIdx.x;
    if (t >= B*E) return;
    int b = t >> 3, e = t & 7;
    float s = rb[e];
    const float* pp = &g_pooled[b*CIN];
    const float* wp = &rw[e*CIN];
    #pragma unroll 8
    for (int i = 0; i < CIN; i++) s = fmaf(pp[i], wp[i], s);
    g_route[t] = 1.f / (1.f + expf(-s));
}

// ---------------------------------------------------------------------------
// Kernel 3: combine experts -> frag-order fp16 weights, smem-staged, 16-co
// blocks, contiguous uint4 writes (R14 variant — fastest measured).
// Grid (16 cic, 4 cot, 4 tile), 256 threads, 73.7 KB dynamic smem.
// ---------------------------------------------------------------------------
__global__ void combine_kernel(const float* __restrict__ kw) {
    extern __shared__ float s_kw[];              // [e][co16][144] = 18432 floats
    __shared__ float r[B*E];
    if (threadIdx.x < B*E) r[threadIdx.x] = g_route[threadIdx.x];

    const int cic  = blockIdx.x;   // 0..15
    const int cot  = blockIdx.y;   // 0..3
    const int tile = blockIdx.z;   // 0..3
    const int co_base = cot * 64 + tile * 16;

    // ---- Phase A: coalesced float4 stage of the 8e x 16co x 144 slab
    #pragma unroll
    for (int k = 0; k < 18; k++) {
        int f4  = threadIdx.x + 256 * k;         // 0..4607
        int e   = f4 / 576;
        int rem = f4 - e * 576;
        int co  = rem / 36;
        int p4  = rem - co * 36;
        const float4* src = (const float4*)(kw +
            ((size_t)(e * COUT + co_base + co) * CIN + cic * CI_C) * TAPS) + p4;
        *(float4*)&s_kw[(e * 16 + co) * 144 + p4 * 4] = *src;
    }
    __syncthreads();

    // ---- Phase B: combine + contiguous uint4 frag writes
    for (int pos = threadIdx.x; pos < 288; pos += 256) {
        int tg  = pos & 3;
        int grp = (pos >> 2) & 7;
        int tap = pos >> 5;

        float w0[4][E], w1[4][E];
        #pragma unroll
        for (int k4 = 0; k4 < 4; k4++) {
            int cohalf = k4 & 1, rrhigh = k4 >> 1;
            int co_l = cohalf * 8 + grp;
            int ci_l = 2 * tg + 8 * rrhigh;
            #pragma unroll
            for (int e = 0; e < E; e++) {
                const float* sp = &s_kw[(e * 16 + co_l) * 144 + ci_l * TAPS + tap];
                w0[k4][e] = sp[0];
                w1[k4][e] = sp[TAPS];
            }
        }

        size_t idx4 = (size_t)tap * 128 + tile * 32 + grp * 4 + tg;  // uint4 units
        uint4* dst = (uint4*)g_cwf + ((size_t)cot * NCHUNK + cic) * (CHUNK_W/4) + idx4;
        const size_t bstride4 = (size_t)4 * NCHUNK * CHUNK_W / 4;
        #pragma unroll
        for (int b = 0; b < B; b++) {
            uint4 v;
            unsigned* vp = (unsigned*)&v;
            #pragma unroll
            for (int k4 = 0; k4 < 4; k4++) {
                float s0 = 0.f, s1 = 0.f;
                #pragma unroll
                for (int e = 0; e < E; e++) {
                    float rv = r[b*E + e];
                    s0 = fmaf(rv, w0[k4][e], s0);
                    s1 = fmaf(rv, w1[k4][e], s1);
                }
                __half2 h = __floats2half2_rn(s0, s1);
                vp[k4] = *(unsigned*)&h;
            }
            dst[(size_t)b * bstride4] = v;
        }
    }
}

// ---------------------------------------------------------------------------
// Kernel 3b: input prep -> g_xin[b][rq][cic][6*480], zero-padded, fp16,
// slot q = 2*tg+h -> ci pair {2tg+8h, 2tg+8h+1}. Smem transpose.
// Grid (14 rq, 16 cic, 16 b), 256 threads.
// ---------------------------------------------------------------------------
__global__ void prep_kernel(const float* __restrict__ x) {
    const int rq = blockIdx.x, cic = blockIdx.y, b = blockIdx.z;
    const float* xb = x + (size_t)b * CIN * HW;
    __shared__ float s[CI_C * 6 * 61];           // padded stride 61

    // phase A: coalesced global reads
    for (int idx = threadIdx.x; idx < CI_C * 6 * 60; idx += 256) {
        int ci  = idx / 360;
        int rem = idx - ci * 360;
        int row = rem / 60;
        int col = rem - row * 60;
        int gr  = rq * RP + row - 1;
        int gc  = col - 1;
        float v = 0.f;
        if ((unsigned)gr < HH && (unsigned)gc < WW)
            v = xb[(cic * CI_C + ci) * HW + gr * WW + gc];
        s[(ci * 6 + row) * 61 + col] = v;
    }
    __syncthreads();

    // phase B: coalesced interleaved fp16 writes
    unsigned* dst = g_xin + ((size_t)(b * NRQ + rq) * NCHUNK + cic) * CHUNK_IN;
    for (int i = threadIdx.x; i < CHUNK_IN; i += 256) {
        int row = i / ROWU;
        int p   = i - row * ROWU;
        int col = p >> 3;
        int q   = p & 7;
        int ci0 = 2 * (q >> 1) + 8 * (q & 1);
        float f0 = s[((ci0    ) * 6 + row) * 61 + col];
        float f1 = s[((ci0 + 1) * 6 + row) * 61 + col];
        __half2 h = __floats2half2_rn(f0, f1);
        dst[i] = *(unsigned*)&h;
    }
}

// ---------------------------------------------------------------------------
// Kernel 4: persistent fp16 mma conv + BN + SiLU, atomic work-stealing.
// Grid = SMs*3 CTAs; each pulls (rq,cot,b) items off g_work. Inner pipeline
// identical to the R14 kernel. Eliminates the ~50us last-wave tail
// (896 items / 444 slots = 6.05 CTAs/SM -> 8 SMs ran 3 rounds).
// ---------------------------------------------------------------------------
__global__ __launch_bounds__(128, 3)
void conv_mma_kernel(const float* __restrict__ bn_gamma,
                     const float* __restrict__ bn_beta,
                     const float* __restrict__ bn_mean,
                     const float* __restrict__ bn_var,
                     float* __restrict__ out) {
    const int tid  = threadIdx.x;
    const int lane = tid & 31;
    const int wid  = tid >> 5;
    const int tg   = lane & 3;
    const int grp  = lane >> 2;

    __shared__ __align__(16) unsigned s_in[2][CHUNK_IN];
    __shared__ __align__(16) unsigned s_w [2][CHUNK_W];
    __shared__ int s_item;

    for (;;) {
        if (tid == 0) s_item = (int)atomicAdd(&g_work, 1u);
        __syncthreads();
        const int item = s_item;
        if (item >= NITEMS) break;

        const int rq   = item % NRQ;       // fastest: consecutive items share weights
        const int cotb = item / NRQ;
        const int cot  = cotb & 3;
        const int b    = cotb >> 2;
        const int co0  = cot * CO_T;
        const int row0 = rq * RP;

        const unsigned* gin = g_xin + (size_t)(b * NRQ + rq) * NCHUNK * CHUNK_IN;
        const unsigned* gw  = g_cwf + (size_t)(b * 4 + cot) * NCHUNK * CHUNK_W;

        float acc[4][7][4];
        #pragma unroll
        for (int t = 0; t < 4; t++)
            #pragma unroll
            for (int j = 0; j < 7; j++)
                #pragma unroll
                for (int q = 0; q < 4; q++) acc[t][j][q] = 0.f;

        auto stage = [&](int c, int sb) {
            unsigned din = smem_u32(&s_in[sb][0]);
            unsigned dw  = smem_u32(&s_w[sb][0]);
            const unsigned* src_in = gin + (size_t)c * CHUNK_IN;
            const unsigned* src_w  = gw  + (size_t)c * CHUNK_W;
            #pragma unroll
            for (int k = 0; k < 6; k++) {
                int i = tid + 128 * k;                 // 16B units, 720 total
                if (i < CHUNK_IN / 4)
                    cpa16(din + 16u * i, src_in + 4 * i);
            }
            #pragma unroll
            for (int k = 0; k < 9; k++) {
                int i = tid + 128 * k;                 // 1152 total
                cpa16(dw + 16u * i, src_w + 4 * i);
            }
        };

        stage(0, 0);
        asm volatile("cp.async.commit_group;");

        for (int c = 0; c < NCHUNK; c++) {
            const int cur = c & 1;
            if (c + 1 < NCHUNK) stage(c + 1, cur ^ 1);
            asm volatile("cp.async.commit_group;");
            asm volatile("cp.async.wait_group 1;");
            __syncthreads();

            #pragma unroll
            for (int kh = 0; kh < 3; kh++) {
                const unsigned* brow = &s_in[cur][(wid + kh) * ROWU];
                #pragma unroll
                for (int kw3 = 0; kw3 < 3; kw3++) {
                    const int tap = kh * 3 + kw3;
                    uint4 a[4];
                    #pragma unroll
                    for (int t = 0; t < 4; t++)
                        a[t] = *(const uint4*)(&s_w[cur][(tap * 4 + t) * 128 + lane * 4]);
                    uint2 bv[7];
                    #pragma unroll
                    for (int j = 0; j < 7; j++)
                        bv[j] = *(const uint2*)(&brow[(j * 8 + grp + kw3) * 8 + tg * 2]);
                    #pragma unroll
                    for (int t = 0; t < 4; t++)
                        #pragma unroll
                        for (int j = 0; j < 7; j++)
                            mma16(acc[t][j], a[t], bv[j]);
                }
            }
            __syncthreads();
        }

        // ---- epilogue: BN + SiLU, float2 stores
        const int orow = row0 + wid;
        #pragma unroll
        for (int t = 0; t < 4; t++) {
            const int c1 = co0 + t * 16 + grp;
            const int c2 = c1 + 8;
            const float inv1 = bn_gamma[c1] * rsqrtf(bn_var[c1] + BN_EPS);
            const float sh1  = bn_beta[c1] - bn_mean[c1] * inv1;
            const float inv2 = bn_gamma[c2] * rsqrtf(bn_var[c2] + BN_EPS);
            const float sh2  = bn_beta[c2] - bn_mean[c2] * inv2;
            float* o1 = out + ((size_t)(b * COUT + c1) * HH + orow) * WW;
            float* o2 = out + ((size_t)(b * COUT + c2) * HH + orow) * WW;
            #pragma unroll
            for (int j = 0; j < 7; j++) {
                int col = j * 8 + 2 * tg;
                float y0 = fmaf(acc[t][j][0], inv1, sh1);
                float y1 = fmaf(acc[t][j][1], inv1, sh1);
                float y2 = fmaf(acc[t][j][2], inv2, sh2);
                float y3 = fmaf(acc[t][j][3], inv2, sh2);
                float2 r1 = make_float2(y0 / (1.f + expf(-y0)), y1 / (1.f + expf(-y1)));
                float2 r2 = make_float2(y2 / (1.f + expf(-y2)), y3 / (1.f + expf(-y3)));
                *(float2*)(o1 + col) = r1;
                *(float2*)(o2 + col) = r2;
            }
        }
    }
}

// ---------------------------------------------------------------------------
// Launch: fork prep onto a side stream; persistent conv sized to SM count.
// ---------------------------------------------------------------------------
extern "C" void kernel_launch(void* const* d_in, const int* in_sizes, int n_in,
                              void* d_out, int out_size) {
    const float* x        = (const float*)d_in[0];
    const float* rw       = (const float*)d_in[1];
    const float* rb       = (const float*)d_in[2];
    const float* kw       = (const float*)d_in[3];
    const float* bn_gamma = (const float*)d_in[4];
    const float* bn_beta  = (const float*)d_in[5];
    const float* bn_mean  = (const float*)d_in[6];
    const float* bn_var   = (const float*)d_in[7];
    float* out = (float*)d_out;

    static cudaStream_t s2 = nullptr;
    static cudaEvent_t evFork = nullptr, evJoin = nullptr;
    static int conv_grid = 0;
    if (s2 == nullptr) {
        cudaStreamCreateWithFlags(&s2, cudaStreamNonBlocking);
        cudaEventCreateWithFlags(&evFork, cudaEventDisableTiming);
        cudaEventCreateWithFlags(&evJoin, cudaEventDisableTiming);
        int nsm = 148;
        cudaDeviceGetAttribute(&nsm, cudaDevAttrMultiProcessorCount, 0);
        conv_grid = nsm * 3;
        if (conv_grid > NITEMS) conv_grid = NITEMS;
    }

    const int combine_smem = E * 16 * 144 * (int)sizeof(float);   // 73728 B
    cudaFuncSetAttribute(combine_kernel,
                         cudaFuncAttributeMaxDynamicSharedMemorySize, combine_smem);

    // fork: prep runs on s2 concurrent with gap -> routing -> combine
    cudaEventRecord(evFork, 0);
    cudaStreamWaitEvent(s2, evFork, 0);
    prep_kernel<<<dim3(NRQ, NCHUNK, B), 256, 0, s2>>>(x);

    gap_kernel<<<B*CIN, 256>>>(x);
    routing_kernel<<<1, 128>>>(rw, rb);
    combine_kernel<<<dim3(NCHUNK, 4, 4), 256, combine_smem>>>(kw);

    // join: conv needs both prep (s2) and combine (default stream)
    cudaEventRecord(evJoin, s2);
    cudaStreamWaitEvent(0, evJoin, 0);
    conv_mma_kernel<<<conv_grid, 128>>>(bn_gamma, bn_beta, bn_mean, bn_var, out);
}